// round 5
// baseline (speedup 1.0000x reference)
#include <cuda_runtime.h>

// Discriminator neural-SDE scan. B=512, T=4096, D=8, H=16, W=16.
// 4 warps / 128 threads per batch element, 512 blocks. Per step:
//   phase1 (warps 0-1): 32 hidden rows, K-halved; each thread keeps its
//     8-element slice of y IN REGISTERS (y[k] += e[k] from SMEM) and
//     recomputes the dot fresh each step (reference-identical rounding).
//   phase2 (all 128): one g-row per thread (dot16 + tanh), einsum partial
//     reduced via atomicAdd into double-buffered SMEM; warp2: f rows
//     (full dots, parallel); warp3: y accumulator + buffer zeroing + readout.
// 2 __syncthreads per step. EX2/RCP-based activations.

#define T_STEPS 4096
#define FULLMASK 0xffffffffu

// tanh(x) = 1 - 2/(exp(2x)+1); EX2-based, branchless, saturates via inf/0.
__device__ __forceinline__ float tanh_fast(float x) {
    float e = __expf(2.f * x);
    return 1.f - __fdividef(2.f, e + 1.f);
}

// lipswish(x) = 0.909 * x * sigmoid(x), EX2-based.
__device__ __forceinline__ float lipswish_fast(float x) {
    return 0.909f * x * __fdividef(1.f, 1.f + __expf(-x));
}

__global__ void __launch_bounds__(128) sde_scan_kernel(
    const float* __restrict__ ts, const float* __restrict__ ys,
    const float* __restrict__ iW1, const float* __restrict__ ib1,
    const float* __restrict__ iW2, const float* __restrict__ ib2,
    const float* __restrict__ vW1, const float* __restrict__ vb1,
    const float* __restrict__ vW2, const float* __restrict__ vb2,
    const float* __restrict__ cW1, const float* __restrict__ cb1,
    const float* __restrict__ cW2, const float* __restrict__ cb2,
    const float* __restrict__ rW, const float* __restrict__ rb,
    float* __restrict__ out)
{
    const int b    = blockIdx.x;
    const int tid  = threadIdx.x;
    const int w    = tid >> 5;
    const int lane = tid & 31;

    __shared__ __align__(16) float s_h[32];      // hidden: [0:16]=hv, [16:32]=hc
    __shared__ __align__(16) float s_f[16];      // f(n)
    __shared__ __align__(16) float s_gy[2][16];  // g·dx, double-buffered

    const float t0 = ts[0];
    const float* __restrict__ ysb = ys + (size_t)b * (T_STEPS * 8);

    // ---- phase-1 weights (warps 0-1): row r1 = tid>>1, khalf = tid&1 ----
    const int r1    = tid >> 1;        // 0..31 valid for tid<64
    const int khalf = tid & 1;
    float w1h[8], yk[8], wtl = 0.f, bb = 0.f;
    if (tid < 64) {
        const float* Wrow = (r1 < 16) ? (vW1 + r1 * 17) : (cW1 + (r1 - 16) * 17);
#pragma unroll
        for (int k = 0; k < 8; k++) w1h[k] = Wrow[1 + khalf * 8 + k];
        if (khalf == 0) {
            wtl = Wrow[0];
            bb  = (r1 < 16) ? vb1[r1] : cb1[r1 - 16];
        }
    }

    // ---- g weights: one flat row per thread: fl = tid, h16 = tid>>3, d = tid&7 ----
    const int h16 = tid >> 3;
    const int dd  = tid & 7;
    float cw2r[16], cb2r;
    cb2r = cb2[tid];
#pragma unroll
    for (int k = 0; k < 16; k++) cw2r[k] = cW2[tid * 16 + k];

    // ---- f weights (warp 2, lanes 0-15): full row `lane` ----
    float vw2r[16], vb2r = 0.f;
#pragma unroll
    for (int k = 0; k < 16; k++) vw2r[k] = 0.f;
    if (w == 2 && lane < 16) {
        vb2r = vb2[lane];
#pragma unroll
        for (int k = 0; k < 16; k++) vw2r[k] = vW2[lane * 16 + k];
    }

    // ---- readout weights (warp 3, lanes 0-15) ----
    float rwr = 0.f;
    if (w == 3 && lane < 16) rwr = rW[lane];

    // ---- initial MLP (warp 0): y0 -> s_h[0..15]; also out[2b] ----
    if (w == 0) {
        float a = 0.f;
        if (lane < 16) {
            a = fmaf(iW1[lane * 9], t0, ib1[lane]);
#pragma unroll
            for (int k = 0; k < 8; k++) a = fmaf(iW1[lane * 9 + 1 + k], ysb[k], a);
            a = fmaxf(a, 0.f);
        }
        float hv[16];
#pragma unroll
        for (int k = 0; k < 16; k++) hv[k] = __shfl_sync(FULLMASK, a, k);
        float y0 = 0.f;
        if (lane < 16) {
            y0 = ib2[lane];
#pragma unroll
            for (int k = 0; k < 16; k++) y0 = fmaf(iW2[lane * 16 + k], hv[k], y0);
            s_h[lane] = y0;
        }
        float yv16[16];
#pragma unroll
        for (int k = 0; k < 16; k++) yv16[k] = __shfl_sync(FULLMASK, y0, k);
        if (lane == 0) {
            float acc = rb[0];
#pragma unroll
            for (int k = 0; k < 16; k++) acc = fmaf(rW[k], yv16[k], acc);
            out[b * 2 + 0] = acc;
        }
    }
    __syncthreads();

    // y0 into registers: phase-1 threads take their khalf slice; warp3 its lane.
    if (tid < 64) {
#pragma unroll
        for (int k = 0; k < 8; k++) yk[k] = s_h[khalf * 8 + k];
    }
    float y_reg = 0.f;
    if (w == 3 && lane < 16) y_reg = s_h[lane];
    if (w == 2 && lane < 16) {
        s_f[lane] = 0.f;
        s_gy[0][lane] = 0.f;
        s_gy[1][lane] = 0.f;
    }
    __syncthreads();

    // ---- dx: each thread tracks ysb[row*8 + dd] ----
    auto ldx = [&](int r) -> float {
        return __ldg(ysb + (size_t)r * 8 + dd);
    };

    float tf = t0;

    // ---- one Euler step; RB = read buffer ((n+1)&1) holds e(n-1) ----
    auto step = [&](int RB, const float xcur, const float xnxt) {
        // ===== phase 1 window =====
        if (w < 2) {
            const float4* sf4 = reinterpret_cast<const float4*>(s_f);
            const float4* sg4 = reinterpret_cast<const float4*>(s_gy[RB]);
            float4 fl = sf4[khalf * 2 + 0], fh = sf4[khalf * 2 + 1];
            float4 gl = sg4[khalf * 2 + 0], gh = sg4[khalf * 2 + 1];
            // y slice update (reference-identical Euler accumulation)
            yk[0] += fl.x + gl.x;  yk[1] += fl.y + gl.y;
            yk[2] += fl.z + gl.z;  yk[3] += fl.w + gl.w;
            yk[4] += fh.x + gh.x;  yk[5] += fh.y + gh.y;
            yk[6] += fh.z + gh.z;  yk[7] += fh.w + gh.w;
            // fresh dot each step (no running-preactivation rounding)
            float a0 = fmaf(wtl, tf, bb), a1 = 0.f, a2 = 0.f, a3 = 0.f;
            a0 = fmaf(w1h[0], yk[0], a0); a1 = fmaf(w1h[1], yk[1], a1);
            a2 = fmaf(w1h[2], yk[2], a2); a3 = fmaf(w1h[3], yk[3], a3);
            a0 = fmaf(w1h[4], yk[4], a0); a1 = fmaf(w1h[5], yk[5], a1);
            a2 = fmaf(w1h[6], yk[6], a2); a3 = fmaf(w1h[7], yk[7], a3);
            float pre = (a0 + a1) + (a2 + a3);
            float tot = pre + __shfl_xor_sync(FULLMASK, pre, 1);
            float hact = lipswish_fast(tot);
            s_h[r1] = hact;                 // both khalf threads store same value
        } else if (w == 3 && lane < 16) {
            // running y accumulator + zero the buffer phase2 will fill (1-RB)
            y_reg += s_f[lane] + s_gy[RB][lane];
            s_gy[1 - RB][lane] = 0.f;
        }
        tf += 1.f;
        __syncthreads();

        // ===== phase 2 =====
        // g row fl = tid from hc = s_h[16..31]
        const float4* sh4 = reinterpret_cast<const float4*>(s_h);
        float4 c0 = sh4[4], c1 = sh4[5], c2 = sh4[6], c3 = sh4[7];
        float a0 = cb2r, a1 = 0.f, a2 = 0.f, a3 = 0.f;
        a0 = fmaf(cw2r[0],  c0.x, a0); a1 = fmaf(cw2r[1],  c0.y, a1);
        a2 = fmaf(cw2r[2],  c0.z, a2); a3 = fmaf(cw2r[3],  c0.w, a3);
        a0 = fmaf(cw2r[4],  c1.x, a0); a1 = fmaf(cw2r[5],  c1.y, a1);
        a2 = fmaf(cw2r[6],  c1.z, a2); a3 = fmaf(cw2r[7],  c1.w, a3);
        a0 = fmaf(cw2r[8],  c2.x, a0); a1 = fmaf(cw2r[9],  c2.y, a1);
        a2 = fmaf(cw2r[10], c2.z, a2); a3 = fmaf(cw2r[11], c2.w, a3);
        a0 = fmaf(cw2r[12], c3.x, a0); a1 = fmaf(cw2r[13], c3.y, a1);
        a2 = fmaf(cw2r[14], c3.z, a2); a3 = fmaf(cw2r[15], c3.w, a3);
        float g = tanh_fast((a0 + a1) + (a2 + a3));
        atomicAdd(&s_gy[1 - RB][h16], g * (xnxt - xcur));

        // f rows (warp 2, lanes 0-15): full dot from hv = s_h[0..15]
        if (w == 2) {
            float4 v0 = sh4[0], v1 = sh4[1], v2 = sh4[2], v3 = sh4[3];
            float f0 = vb2r, f1 = 0.f, f2 = 0.f, f3 = 0.f;
            f0 = fmaf(vw2r[0],  v0.x, f0); f1 = fmaf(vw2r[1],  v0.y, f1);
            f2 = fmaf(vw2r[2],  v0.z, f2); f3 = fmaf(vw2r[3],  v0.w, f3);
            f0 = fmaf(vw2r[4],  v1.x, f0); f1 = fmaf(vw2r[5],  v1.y, f1);
            f2 = fmaf(vw2r[6],  v1.z, f2); f3 = fmaf(vw2r[7],  v1.w, f3);
            f0 = fmaf(vw2r[8],  v2.x, f0); f1 = fmaf(vw2r[9],  v2.y, f1);
            f2 = fmaf(vw2r[10], v2.z, f2); f3 = fmaf(vw2r[11], v2.w, f3);
            f0 = fmaf(vw2r[12], v3.x, f0); f1 = fmaf(vw2r[13], v3.y, f1);
            f2 = fmaf(vw2r[14], v3.z, f2); f3 = fmaf(vw2r[15], v3.w, f3);
            float fv = tanh_fast((f0 + f1) + (f2 + f3));
            if (lane < 16) s_f[lane] = fv;
        }
        __syncthreads();
    };

    // ---- main loop: 4-step bodies, register-rotated scalar prefetch ----
    float xA = ldx(0), xB = ldx(1), xC = ldx(2), xD = ldx(3);
    int n = 0;
#pragma unroll 1
    for (int it = 0; it < 1023; it++) {   // n = 0..4091
        float p0 = ldx(n + 4);
        step(1, xA, xB);                  // n   (even): RB=1
        float p1 = ldx(n + 5);
        step(0, xB, xC);                  // n+1 (odd):  RB=0
        float p2 = ldx(n + 6);
        step(1, xC, xD);                  // n+2: RB=1
        float p3 = ldx(n + 7);
        step(0, xD, p0);                  // n+3: RB=0
        xA = p0; xB = p1; xC = p2; xD = p3;
        n += 4;
    }
    // tail: n = 4092 (RB=1), 4093 (RB=0), 4094 (RB=1)
    step(1, xA, xB);
    step(0, xB, xC);
    step(1, xC, xD);

    // ---- readout of yT: e(4094) sits in s_f and s_gy[0] ----
    if (w == 3 && lane < 16) {
        float yfin = y_reg + s_f[lane] + s_gy[0][lane];
        float acc = rwr * yfin;
        acc += __shfl_xor_sync(FULLMASK, acc, 1);
        acc += __shfl_xor_sync(FULLMASK, acc, 2);
        acc += __shfl_xor_sync(FULLMASK, acc, 4);
        acc += __shfl_xor_sync(FULLMASK, acc, 8);
        if (lane == 0) out[b * 2 + 1] = acc + rb[0];
    }
}

extern "C" void kernel_launch(void* const* d_in, const int* in_sizes, int n_in,
                              void* d_out, int out_size) {
    const float* ts  = (const float*)d_in[0];
    const float* ys  = (const float*)d_in[1];
    const float* iW1 = (const float*)d_in[2];
    const float* ib1 = (const float*)d_in[3];
    const float* iW2 = (const float*)d_in[4];
    const float* ib2 = (const float*)d_in[5];
    const float* vW1 = (const float*)d_in[6];
    const float* vb1 = (const float*)d_in[7];
    const float* vW2 = (const float*)d_in[8];
    const float* vb2 = (const float*)d_in[9];
    const float* cW1 = (const float*)d_in[10];
    const float* cb1 = (const float*)d_in[11];
    const float* cW2 = (const float*)d_in[12];
    const float* cb2 = (const float*)d_in[13];
    const float* rW  = (const float*)d_in[14];
    const float* rb  = (const float*)d_in[15];

    const int Bn = out_size / 2;  // (B, 2, 1) float32
    sde_scan_kernel<<<Bn, 128>>>(ts, ys, iW1, ib1, iW2, ib2,
                                 vW1, vb1, vW2, vb2,
                                 cW1, cb1, cW2, cb2, rW, rb,
                                 (float*)d_out);
}

// round 6
// speedup vs baseline: 1.4602x; 1.4602x over previous
#include <cuda_runtime.h>

// Discriminator neural-SDE scan. B=512, T=4096, D=8, H=16, W=16.
// 2 warps / 64 threads per batch element, 512 blocks.
// Per step (2 barriers):
//   phase2 (all 64): 2 g-rows/thread (packed f32x2 dot + tanh), einsum d-pair
//     partial -> s_part[dp][h] via plain STS (no atomics, no shfl chain);
//     lanes 16-23 of each warp: 8 f-rows each warp (packed dot + tanh) -> s_f.
//   phase1 (lanes 0-15 of each warp): full y[16] in registers (packed pairs);
//     e = tree-sum of 4 partials + f (packed adds); y += e; full-row 17-term
//     dot (packed, no shfl) + lipswish -> s_h.
// EX2/RCP-based activations (accuracy-safe).

#define T_STEPS 4096
#define FULLMASK 0xffffffffu
typedef unsigned long long ull;

__device__ __forceinline__ ull add2(ull a, ull b) {
    ull r; asm("add.rn.f32x2 %0, %1, %2;" : "=l"(r) : "l"(a), "l"(b)); return r;
}
__device__ __forceinline__ ull fma2(ull a, ull b, ull c) {
    ull r; asm("fma.rn.f32x2 %0, %1, %2, %3;" : "=l"(r) : "l"(a), "l"(b), "l"(c)); return r;
}
__device__ __forceinline__ ull pack2(float x, float y) {
    ull r; asm("mov.b64 %0, {%1,%2};" : "=l"(r) : "f"(x), "f"(y)); return r;
}
__device__ __forceinline__ float2 unpack2(ull v) {
    float2 r; asm("mov.b64 {%0,%1}, %2;" : "=f"(r.x), "=f"(r.y) : "l"(v)); return r;
}

// tanh(x) = 1 - 2/(exp(2x)+1); EX2-based, branchless, saturates via inf/0.
__device__ __forceinline__ float tanh_fast(float x) {
    float e = __expf(2.f * x);
    return 1.f - __fdividef(2.f, e + 1.f);
}
// lipswish(x) = 0.909 * x * sigmoid(x); 0.909*x computed off the MUFU chain.
__device__ __forceinline__ float lipswish_fast(float x) {
    float ax = 0.909f * x;
    return ax * __fdividef(1.f, 1.f + __expf(-x));
}

__global__ void __launch_bounds__(64) sde_scan_kernel(
    const float* __restrict__ ts, const float* __restrict__ ys,
    const float* __restrict__ iW1, const float* __restrict__ ib1,
    const float* __restrict__ iW2, const float* __restrict__ ib2,
    const float* __restrict__ vW1, const float* __restrict__ vb1,
    const float* __restrict__ vW2, const float* __restrict__ vb2,
    const float* __restrict__ cW1, const float* __restrict__ cb1,
    const float* __restrict__ cW2, const float* __restrict__ cb2,
    const float* __restrict__ rW, const float* __restrict__ rb,
    float* __restrict__ out)
{
    const int b    = blockIdx.x;
    const int tid  = threadIdx.x;
    const int w    = tid >> 5;
    const int lane = tid & 31;

    __shared__ __align__(16) float s_h[32];        // hidden: [0:16]=hv, [16:32]=hc
    __shared__ __align__(16) float s_f[16];        // f(n)
    __shared__ __align__(16) float s_part[4][16];  // einsum partials [dpair][h]
    __shared__ __align__(16) float s_y0[16];

    const float t0 = ts[0];
    const float* __restrict__ ysb = ys + (size_t)b * (T_STEPS * 8);

    // ---- roles ----
    const bool isP1 = (lane < 16);
    const int  r1   = w * 16 + lane;          // hidden row (isP1)
    const int  h16  = w * 8 + (lane >> 2);    // g output h (all threads)
    const int  dp   = lane & 3;               // d-pair index
    const int  d0   = dp * 2;
    const bool isF  = (lane >= 16 && lane < 24);
    const int  frow = w * 8 + (lane - 16);    // f row (isF)

    // ---- phase-1 weights: full row [t-coef | 16 y-coefs], packed pairs ----
    ull w1p[8]; float w1t = 0.f, b1r = 0.f;
    ull yk[8];
#pragma unroll
    for (int j = 0; j < 8; j++) { w1p[j] = 0; yk[j] = 0; }
    if (isP1) {
        const float* W = (w == 0) ? (vW1 + lane * 17) : (cW1 + lane * 17);
        w1t = W[0];
#pragma unroll
        for (int j = 0; j < 8; j++) w1p[j] = pack2(W[1 + 2 * j], W[2 + 2 * j]);
        b1r = (w == 0) ? vb1[lane] : cb1[lane];
    }

    // ---- g weights: rows fl0 = h16*8 + d0, fl0+1 (16B-aligned rows) ----
    ull cga[8], cgb[8]; float cba, cbb;
    {
        const int fl0 = h16 * 8 + d0;
        const ulonglong2* A  = reinterpret_cast<const ulonglong2*>(cW2 + fl0 * 16);
        const ulonglong2* Bt = reinterpret_cast<const ulonglong2*>(cW2 + (fl0 + 1) * 16);
#pragma unroll
        for (int q = 0; q < 4; q++) {
            ulonglong2 u = A[q];  cga[2 * q] = u.x; cga[2 * q + 1] = u.y;
            ulonglong2 v = Bt[q]; cgb[2 * q] = v.x; cgb[2 * q + 1] = v.y;
        }
        cba = cb2[fl0]; cbb = cb2[fl0 + 1];
    }

    // ---- f weights (isF): full row frow, packed ----
    ull vw2p[8]; float vb2r = 0.f;
#pragma unroll
    for (int j = 0; j < 8; j++) vw2p[j] = 0;
    if (isF) {
        const ulonglong2* V = reinterpret_cast<const ulonglong2*>(vW2 + frow * 16);
#pragma unroll
        for (int q = 0; q < 4; q++) {
            ulonglong2 u = V[q]; vw2p[2 * q] = u.x; vw2p[2 * q + 1] = u.y;
        }
        vb2r = vb2[frow];
    }

    // ---- initial MLP (warp 0): y0 -> s_y0; out[2b] ----
    if (w == 0) {
        float a = 0.f;
        if (lane < 16) {
            a = fmaf(iW1[lane * 9], t0, ib1[lane]);
#pragma unroll
            for (int k = 0; k < 8; k++) a = fmaf(iW1[lane * 9 + 1 + k], ysb[k], a);
            a = fmaxf(a, 0.f);
        }
        float hv[16];
#pragma unroll
        for (int k = 0; k < 16; k++) hv[k] = __shfl_sync(FULLMASK, a, k);
        float y0 = 0.f;
        if (lane < 16) {
            y0 = ib2[lane];
#pragma unroll
            for (int k = 0; k < 16; k++) y0 = fmaf(iW2[lane * 16 + k], hv[k], y0);
            s_y0[lane] = y0;
        }
        float yv16[16];
#pragma unroll
        for (int k = 0; k < 16; k++) yv16[k] = __shfl_sync(FULLMASK, y0, k);
        if (lane == 0) {
            float acc = rb[0];
#pragma unroll
            for (int k = 0; k < 16; k++) acc = fmaf(rW[k], yv16[k], acc);
            out[b * 2 + 0] = acc;
        }
    }
    __syncthreads();

    // y0 into packed registers of phase-1 lanes; compute h(0) at t0
    if (isP1) {
        const ulonglong2* Y = reinterpret_cast<const ulonglong2*>(s_y0);
#pragma unroll
        for (int q = 0; q < 4; q++) {
            ulonglong2 u = Y[q]; yk[2 * q] = u.x; yk[2 * q + 1] = u.y;
        }
        ull a0 = 0, a1 = 0;
#pragma unroll
        for (int j = 0; j < 8; j += 2) {
            a0 = fma2(w1p[j],     yk[j],     a0);
            a1 = fma2(w1p[j + 1], yk[j + 1], a1);
        }
        float2 fa = unpack2(a0), fb = unpack2(a1);
        float pre = ((fa.x + fa.y) + (fb.x + fb.y)) + fmaf(w1t, t0, b1r);
        s_h[r1] = lipswish_fast(pre);
    }
    __syncthreads();

    // ---- dx: per-thread float2 at columns d0, d0+1 ----
    auto ldx = [&](int r) -> float2 {
        return *reinterpret_cast<const float2*>(ysb + (size_t)r * 8 + d0);
    };

    float tf = t0;

    // ---- one Euler step ----
    auto step = [&](const float2 xc, const float2 xn) {
        // ===== phase 2: g rows (all) + f rows (isF) from s_h =====
        ull hc[8];
        {
            const ulonglong2* Hc = reinterpret_cast<const ulonglong2*>(s_h + 16);
#pragma unroll
            for (int q = 0; q < 4; q++) {
                ulonglong2 u = Hc[q]; hc[2 * q] = u.x; hc[2 * q + 1] = u.y;
            }
        }
        ull a0 = 0, a1 = 0, b0 = 0, b1 = 0;
#pragma unroll
        for (int j = 0; j < 8; j += 2) {
            a0 = fma2(cga[j],     hc[j],     a0);
            a1 = fma2(cga[j + 1], hc[j + 1], a1);
            b0 = fma2(cgb[j],     hc[j],     b0);
            b1 = fma2(cgb[j + 1], hc[j + 1], b1);
        }
        float2 A0 = unpack2(a0), A1 = unpack2(a1);
        float2 B0 = unpack2(b0), B1 = unpack2(b1);
        float g0 = tanh_fast(((A0.x + A0.y) + (A1.x + A1.y)) + cba);
        float g1 = tanh_fast(((B0.x + B0.y) + (B1.x + B1.y)) + cbb);
        float part = fmaf(g1, xn.y - xc.y, g0 * (xn.x - xc.x));
        s_part[dp][h16] = part;

        if (isF) {
            ull hv[8];
            const ulonglong2* Hv = reinterpret_cast<const ulonglong2*>(s_h);
#pragma unroll
            for (int q = 0; q < 4; q++) {
                ulonglong2 u = Hv[q]; hv[2 * q] = u.x; hv[2 * q + 1] = u.y;
            }
            ull f0 = 0, f1 = 0;
#pragma unroll
            for (int j = 0; j < 8; j += 2) {
                f0 = fma2(vw2p[j],     hv[j],     f0);
                f1 = fma2(vw2p[j + 1], hv[j + 1], f1);
            }
            float2 F0 = unpack2(f0), F1 = unpack2(f1);
            s_f[frow] = tanh_fast(((F0.x + F0.y) + (F1.x + F1.y)) + vb2r);
        }
        __syncthreads();

        // ===== phase 1: e = f + Σ_dp part; y += e; fresh full-row dot =====
        if (isP1) {
            const ulonglong2* P0 = reinterpret_cast<const ulonglong2*>(s_part[0]);
            const ulonglong2* P1 = reinterpret_cast<const ulonglong2*>(s_part[1]);
            const ulonglong2* P2 = reinterpret_cast<const ulonglong2*>(s_part[2]);
            const ulonglong2* P3 = reinterpret_cast<const ulonglong2*>(s_part[3]);
            const ulonglong2* Fq = reinterpret_cast<const ulonglong2*>(s_f);
#pragma unroll
            for (int q = 0; q < 4; q++) {
                ulonglong2 u0 = P0[q], u1 = P1[q], u2 = P2[q], u3 = P3[q], uf = Fq[q];
                ull ex = add2(add2(add2(u0.x, u1.x), add2(u2.x, u3.x)), uf.x);
                ull ey = add2(add2(add2(u0.y, u1.y), add2(u2.y, u3.y)), uf.y);
                yk[2 * q]     = add2(yk[2 * q],     ex);
                yk[2 * q + 1] = add2(yk[2 * q + 1], ey);
            }
            ull c0 = 0, c1 = 0;
#pragma unroll
            for (int j = 0; j < 8; j += 2) {
                c0 = fma2(w1p[j],     yk[j],     c0);
                c1 = fma2(w1p[j + 1], yk[j + 1], c1);
            }
            float2 fa = unpack2(c0), fb = unpack2(c1);
            float pre = ((fa.x + fa.y) + (fb.x + fb.y)) + fmaf(w1t, tf + 1.f, b1r);
            s_h[r1] = lipswish_fast(pre);
        }
        tf += 1.f;
        __syncthreads();
    };

    // ---- main loop: 4-step bodies, register-rotated float2 prefetch ----
    float2 xA = ldx(0), xB = ldx(1), xC = ldx(2), xD = ldx(3);
    int n = 0;
#pragma unroll 1
    for (int it = 0; it < 1023; it++) {   // n = 0..4091, prefetch rows n+4..n+7 <= 4095
        float2 p0 = ldx(n + 4);
        step(xA, xB);
        float2 p1 = ldx(n + 5);
        step(xB, xC);
        float2 p2 = ldx(n + 6);
        step(xC, xD);
        float2 p3 = ldx(n + 7);
        step(xD, p0);
        xA = p0; xB = p1; xC = p2; xD = p3;
        n += 4;
    }
    // tail: n = 4092, 4093, 4094 (rows already resident)
    step(xA, xB);
    step(xB, xC);
    step(xC, xD);

    // ---- readout of yT: yk of warp0 lane0 holds y(4095) ----
    if (w == 0 && lane == 0) {
        float acc = rb[0];
#pragma unroll
        for (int j = 0; j < 8; j++) {
            float2 v = unpack2(yk[j]);
            acc = fmaf(rW[2 * j],     v.x, acc);
            acc = fmaf(rW[2 * j + 1], v.y, acc);
        }
        out[b * 2 + 1] = acc;
    }
}

extern "C" void kernel_launch(void* const* d_in, const int* in_sizes, int n_in,
                              void* d_out, int out_size) {
    const float* ts  = (const float*)d_in[0];
    const float* ys  = (const float*)d_in[1];
    const float* iW1 = (const float*)d_in[2];
    const float* ib1 = (const float*)d_in[3];
    const float* iW2 = (const float*)d_in[4];
    const float* ib2 = (const float*)d_in[5];
    const float* vW1 = (const float*)d_in[6];
    const float* vb1 = (const float*)d_in[7];
    const float* vW2 = (const float*)d_in[8];
    const float* vb2 = (const float*)d_in[9];
    const float* cW1 = (const float*)d_in[10];
    const float* cb1 = (const float*)d_in[11];
    const float* cW2 = (const float*)d_in[12];
    const float* cb2 = (const float*)d_in[13];
    const float* rW  = (const float*)d_in[14];
    const float* rb  = (const float*)d_in[15];

    const int Bn = out_size / 2;  // (B, 2, 1) float32
    sde_scan_kernel<<<Bn, 64>>>(ts, ys, iW1, ib1, iW2, ib2,
                                vW1, vb1, vW2, vb2,
                                cW1, cb1, cW2, cb2, rW, rb,
                                (float*)d_out);
}

// round 7
// speedup vs baseline: 1.5649x; 1.0717x over previous
#include <cuda_runtime.h>

// Discriminator neural-SDE scan. B=512, T=4096, D=8, H=16, W=16.
// 4 warps / 128 threads per batch element, 512 blocks. Role split:
//   warps 0-1 ("hf"): phase1 = 32 hidden rows (K-split lane pairs) via SPLIT
//     dot W1*(s_w) + W1*(s_f[prev])  [y = w + f_prev never materialized];
//     phase2 = 16 f rows (K-split on lanes 0-15) -> s_f[cur] (double buffer).
//   warps 2-3 ("g"):  phase2 = 128 g rows (2/lane, dot16+tanh), einsum via
//     2-level shfl tree, then w-update: ycur_w += f_prev[h] + part -> s_w.
//     Shifted state: w(n) = y(n+1) - f(n); h-dot adds f back via split dot.
// 2 __syncthreads per step, no atomics, no replicated updates.

#define T_STEPS 4096
#define FULLMASK 0xffffffffu

// tanh(x) = 1 - 2/(exp(2x)+1); EX2-based, branchless, saturates via inf/0.
__device__ __forceinline__ float tanh_fast(float x) {
    float e = __expf(2.f * x);
    return 1.f - __fdividef(2.f, e + 1.f);
}
// lipswish(x) = 0.909 * x * sigmoid(x), EX2-based.
__device__ __forceinline__ float lipswish_fast(float x) {
    float ax = 0.909f * x;
    return ax * __fdividef(1.f, 1.f + __expf(-x));
}

__global__ void __launch_bounds__(128) sde_scan_kernel(
    const float* __restrict__ ts, const float* __restrict__ ys,
    const float* __restrict__ iW1, const float* __restrict__ ib1,
    const float* __restrict__ iW2, const float* __restrict__ ib2,
    const float* __restrict__ vW1, const float* __restrict__ vb1,
    const float* __restrict__ vW2, const float* __restrict__ vb2,
    const float* __restrict__ cW1, const float* __restrict__ cb1,
    const float* __restrict__ cW2, const float* __restrict__ cb2,
    const float* __restrict__ rW, const float* __restrict__ rb,
    float* __restrict__ out)
{
    const int b    = blockIdx.x;
    const int tid  = threadIdx.x;
    const int w    = tid >> 5;
    const int lane = tid & 31;

    __shared__ __align__(16) float s_h[32];     // hidden: [0:16]=hv, [16:32]=hc
    __shared__ __align__(16) float s_w[16];     // w(n) = y(n+1) - f(n)
    __shared__ __align__(16) float s_f[2][16];  // f, double-buffered by step parity

    const float t0 = ts[0];
    const float* __restrict__ ysb = ys + (size_t)b * (T_STEPS * 8);

    const bool isHF = (w < 2);
    const bool isG  = !isHF;
    const int  khalf = lane & 1;

    // ---- hf phase-1 weights: row r1 = w*16 + (lane>>1), K-half khalf ----
    const int r1 = w * 16 + (lane >> 1);
    float w1h[8], wtl = 0.f, bb = 0.f;
#pragma unroll
    for (int k = 0; k < 8; k++) w1h[k] = 0.f;
    if (isHF) {
        const int rr = lane >> 1;
        const float* Wrow = (w == 0) ? (vW1 + rr * 17) : (cW1 + rr * 17);
#pragma unroll
        for (int k = 0; k < 8; k++) w1h[k] = Wrow[1 + khalf * 8 + k];
        if (khalf == 0) {
            wtl = Wrow[0];
            bb  = (w == 0) ? vb1[rr] : cb1[rr];
        }
    }

    // ---- hf phase-2 f weights: lanes 0-15, row frow = w*8 + (lane>>1) ----
    const int frow = w * 8 + (lane >> 1);
    float vfh[8], fbb = 0.f;
#pragma unroll
    for (int k = 0; k < 8; k++) vfh[k] = 0.f;
    if (isHF && lane < 16) {
#pragma unroll
        for (int k = 0; k < 8; k++) vfh[k] = vW2[frow * 16 + khalf * 8 + k];
        if (khalf == 0) fbb = vb2[frow];
    }

    // ---- g weights: gl in [0,64), rows 2gl, 2gl+1; h16 = gl>>2, dp = gl&3 ----
    const int gl  = isG ? ((w - 2) * 32 + lane) : 0;
    const int h16 = gl >> 2;
    const int dp  = gl & 3;
    const int d0  = 2 * dp;
    float cgaw[16], cgbw[16], cba, cbb;
    {
        const int fl0 = 2 * gl;
        const float4* A  = reinterpret_cast<const float4*>(cW2 + fl0 * 16);
        const float4* Bt = reinterpret_cast<const float4*>(cW2 + (fl0 + 1) * 16);
#pragma unroll
        for (int q = 0; q < 4; q++) {
            float4 u = A[q];
            cgaw[4*q+0]=u.x; cgaw[4*q+1]=u.y; cgaw[4*q+2]=u.z; cgaw[4*q+3]=u.w;
            float4 v = Bt[q];
            cgbw[4*q+0]=v.x; cgbw[4*q+1]=v.y; cgbw[4*q+2]=v.z; cgbw[4*q+3]=v.w;
        }
        cba = cb2[fl0]; cbb = cb2[fl0 + 1];
    }

    // ---- initial MLP (warp 0): y0 -> s_w; out[2b]. warp1 zeroes s_f. ----
    if (w == 0) {
        float a = 0.f;
        if (lane < 16) {
            a = fmaf(iW1[lane * 9], t0, ib1[lane]);
#pragma unroll
            for (int k = 0; k < 8; k++) a = fmaf(iW1[lane * 9 + 1 + k], ysb[k], a);
            a = fmaxf(a, 0.f);
        }
        float hv[16];
#pragma unroll
        for (int k = 0; k < 16; k++) hv[k] = __shfl_sync(FULLMASK, a, k);
        float y0 = 0.f;
        if (lane < 16) {
            y0 = ib2[lane];
#pragma unroll
            for (int k = 0; k < 16; k++) y0 = fmaf(iW2[lane * 16 + k], hv[k], y0);
            s_w[lane] = y0;              // w(init) = y(0), f(-1) = 0
        }
        float yv16[16];
#pragma unroll
        for (int k = 0; k < 16; k++) yv16[k] = __shfl_sync(FULLMASK, y0, k);
        if (lane == 0) {
            float acc = rb[0];
#pragma unroll
            for (int k = 0; k < 16; k++) acc = fmaf(rW[k], yv16[k], acc);
            out[b * 2 + 0] = acc;
        }
    }
    if (w == 1 && lane < 16) {
        s_f[0][lane] = 0.f;
        s_f[1][lane] = 0.f;
    }
    __syncthreads();

    // g-lanes: canonical running w in registers
    float ycur_w = s_w[h16];
    float tf = t0;

    // ---- dx: g-lanes track columns d0, d0+1 ----
    auto ldx = [&](int r) -> float2 {
        float2 v = make_float2(0.f, 0.f);
        if (isG) v = *reinterpret_cast<const float2*>(ysb + (size_t)r * 8 + d0);
        return v;
    };

    // ---- one Euler step; RB = (n+1)&1 holds f(n-1); WB = n&1 gets f(n) ----
    auto step = [&](int RB, int WB, const float2 xc, const float2 xn) {
        // ===== phase 1: h(n) = lipswish(W1·(w + f_prev) + wt*t + b) =====
        if (isHF) {
            const float4* W4 = reinterpret_cast<const float4*>(s_w);
            const float4* F4 = reinterpret_cast<const float4*>(s_f[RB]);
            float4 wa = W4[khalf * 2 + 0], wb = W4[khalf * 2 + 1];
            float4 fa = F4[khalf * 2 + 0], fb = F4[khalf * 2 + 1];
            float a0 = fmaf(wtl, tf, bb), a1 = 0.f, a2 = 0.f, a3 = 0.f;
            a0 = fmaf(w1h[0], wa.x, a0); a1 = fmaf(w1h[1], wa.y, a1);
            a2 = fmaf(w1h[2], wa.z, a2); a3 = fmaf(w1h[3], wa.w, a3);
            a0 = fmaf(w1h[4], wb.x, a0); a1 = fmaf(w1h[5], wb.y, a1);
            a2 = fmaf(w1h[6], wb.z, a2); a3 = fmaf(w1h[7], wb.w, a3);
            a0 = fmaf(w1h[0], fa.x, a0); a1 = fmaf(w1h[1], fa.y, a1);
            a2 = fmaf(w1h[2], fa.z, a2); a3 = fmaf(w1h[3], fa.w, a3);
            a0 = fmaf(w1h[4], fb.x, a0); a1 = fmaf(w1h[5], fb.y, a1);
            a2 = fmaf(w1h[6], fb.z, a2); a3 = fmaf(w1h[7], fb.w, a3);
            float pre = (a0 + a1) + (a2 + a3);
            pre += __shfl_xor_sync(FULLMASK, pre, 1);
            float h = lipswish_fast(pre);
            if (khalf == 0) s_h[r1] = h;
            tf += 1.f;
        }
        __syncthreads();

        // ===== phase 2 =====
        if (isG) {
            float fprev = s_f[RB][h16];   // f(n-1)[h], stable this phase
            const float4* H4 = reinterpret_cast<const float4*>(s_h + 16);
            float4 c0 = H4[0], c1 = H4[1], c2 = H4[2], c3 = H4[3];
            float a0 = cba, a1 = 0.f, a2 = 0.f, a3 = 0.f;
            float b0 = cbb, b1 = 0.f, b2 = 0.f, b3 = 0.f;
            a0 = fmaf(cgaw[0],  c0.x, a0); a1 = fmaf(cgaw[1],  c0.y, a1);
            a2 = fmaf(cgaw[2],  c0.z, a2); a3 = fmaf(cgaw[3],  c0.w, a3);
            b0 = fmaf(cgbw[0],  c0.x, b0); b1 = fmaf(cgbw[1],  c0.y, b1);
            b2 = fmaf(cgbw[2],  c0.z, b2); b3 = fmaf(cgbw[3],  c0.w, b3);
            a0 = fmaf(cgaw[4],  c1.x, a0); a1 = fmaf(cgaw[5],  c1.y, a1);
            a2 = fmaf(cgaw[6],  c1.z, a2); a3 = fmaf(cgaw[7],  c1.w, a3);
            b0 = fmaf(cgbw[4],  c1.x, b0); b1 = fmaf(cgbw[5],  c1.y, b1);
            b2 = fmaf(cgbw[6],  c1.z, b2); b3 = fmaf(cgbw[7],  c1.w, b3);
            a0 = fmaf(cgaw[8],  c2.x, a0); a1 = fmaf(cgaw[9],  c2.y, a1);
            a2 = fmaf(cgaw[10], c2.z, a2); a3 = fmaf(cgaw[11], c2.w, a3);
            b0 = fmaf(cgbw[8],  c2.x, b0); b1 = fmaf(cgbw[9],  c2.y, b1);
            b2 = fmaf(cgbw[10], c2.z, b2); b3 = fmaf(cgbw[11], c2.w, b3);
            a0 = fmaf(cgaw[12], c3.x, a0); a1 = fmaf(cgaw[13], c3.y, a1);
            a2 = fmaf(cgaw[14], c3.z, a2); a3 = fmaf(cgaw[15], c3.w, a3);
            b0 = fmaf(cgbw[12], c3.x, b0); b1 = fmaf(cgbw[13], c3.y, b1);
            b2 = fmaf(cgbw[14], c3.z, b2); b3 = fmaf(cgbw[15], c3.w, b3);
            float g0 = tanh_fast((a0 + a1) + (a2 + a3));
            float g1 = tanh_fast((b0 + b1) + (b2 + b3));
            float part = fmaf(g1, xn.y - xc.y, g0 * (xn.x - xc.x));
            part += __shfl_xor_sync(FULLMASK, part, 1);
            part += __shfl_xor_sync(FULLMASK, part, 2);
            // w(n) = w(n-1) + f(n-1) + g(n)·dx(n)  => y(n+1) = w(n) + f(n)
            ycur_w += fprev + part;
            if (dp == 0) s_w[h16] = ycur_w;
        } else if (lane < 16) {
            const float4* H4 = reinterpret_cast<const float4*>(s_h);
            float4 va = H4[khalf * 2 + 0], vb = H4[khalf * 2 + 1];
            float f0 = fbb, f1 = 0.f, f2 = 0.f, f3 = 0.f;
            f0 = fmaf(vfh[0], va.x, f0); f1 = fmaf(vfh[1], va.y, f1);
            f2 = fmaf(vfh[2], va.z, f2); f3 = fmaf(vfh[3], va.w, f3);
            f0 = fmaf(vfh[4], vb.x, f0); f1 = fmaf(vfh[5], vb.y, f1);
            f2 = fmaf(vfh[6], vb.z, f2); f3 = fmaf(vfh[7], vb.w, f3);
            float fp = (f0 + f1) + (f2 + f3);
            fp += __shfl_xor_sync(0x0000ffffu, fp, 1);
            float fv = tanh_fast(fp);
            if (khalf == 0) s_f[WB][frow] = fv;
        }
        __syncthreads();
    };

    // ---- main loop: 4-step bodies, register-rotated float2 prefetch ----
    float2 xA = ldx(0), xB = ldx(1), xC = ldx(2), xD = ldx(3);
    int n = 0;
#pragma unroll 1
    for (int it = 0; it < 1023; it++) {   // n = 0..4091
        float2 p0 = ldx(n + 4);
        step(1, 0, xA, xB);               // n   even: RB=1, WB=0
        float2 p1 = ldx(n + 5);
        step(0, 1, xB, xC);               // n+1 odd:  RB=0, WB=1
        float2 p2 = ldx(n + 6);
        step(1, 0, xC, xD);
        float2 p3 = ldx(n + 7);
        step(0, 1, xD, p0);
        xA = p0; xB = p1; xC = p2; xD = p3;
        n += 4;
    }
    // tail: n = 4092 (RB1,WB0), 4093 (RB0,WB1), 4094 (RB1,WB0)
    step(1, 0, xA, xB);
    step(0, 1, xB, xC);
    step(1, 0, xC, xD);

    // ---- readout: y(4095) = s_w + s_f[0] (last WB = 0) ----
    if (tid == 0) {
        float acc = rb[0];
#pragma unroll
        for (int k = 0; k < 16; k++) acc = fmaf(rW[k], s_w[k] + s_f[0][k], acc);
        out[b * 2 + 1] = acc;
    }
}

extern "C" void kernel_launch(void* const* d_in, const int* in_sizes, int n_in,
                              void* d_out, int out_size) {
    const float* ts  = (const float*)d_in[0];
    const float* ys  = (const float*)d_in[1];
    const float* iW1 = (const float*)d_in[2];
    const float* ib1 = (const float*)d_in[3];
    const float* iW2 = (const float*)d_in[4];
    const float* ib2 = (const float*)d_in[5];
    const float* vW1 = (const float*)d_in[6];
    const float* vb1 = (const float*)d_in[7];
    const float* vW2 = (const float*)d_in[8];
    const float* vb2 = (const float*)d_in[9];
    const float* cW1 = (const float*)d_in[10];
    const float* cb1 = (const float*)d_in[11];
    const float* cW2 = (const float*)d_in[12];
    const float* cb2 = (const float*)d_in[13];
    const float* rW  = (const float*)d_in[14];
    const float* rb  = (const float*)d_in[15];

    const int Bn = out_size / 2;  // (B, 2, 1) float32
    sde_scan_kernel<<<Bn, 128>>>(ts, ys, iW1, ib1, iW2, ib2,
                                 vW1, vb1, vW2, vb2,
                                 cW1, cb1, cW2, cb2, rW, rb,
                                 (float*)d_out);
}

// round 8
// speedup vs baseline: 3.2876x; 2.1008x over previous
#include <cuda_runtime.h>

// Discriminator neural-SDE scan. B=512, T=4096, D=8, H=16, W=16.
// ONE warp per batch element (512 x 32). No block barriers; 2 __syncwarp/step.
//   P1: lane -> hidden row (0-15 vW1, 16-31 cW1), full 17-dot on y from SMEM
//       (4x LDS.128). hc stored DUPLICATED as float2(h,h) for packed consumers.
//   P2: lane -> g rows 4l..4l+3 (two fma.rn.f32x2 packed dots), f row l>>1
//       (K-split + shfl_xor), einsum d-quad + shfl_xor; h = l>>1 everywhere so
//       y update is lane-local; even lane stores s_y[h].
// EX2/RCP-based activations (accuracy-safe).

#define T_STEPS 4096
#define FULLMASK 0xffffffffu
typedef unsigned long long ull;

__device__ __forceinline__ ull fma2(ull a, ull b, ull c) {
    ull r; asm("fma.rn.f32x2 %0, %1, %2, %3;" : "=l"(r) : "l"(a), "l"(b), "l"(c)); return r;
}
__device__ __forceinline__ ull pack2(float x, float y) {
    ull r; asm("mov.b64 %0, {%1,%2};" : "=l"(r) : "f"(x), "f"(y)); return r;
}
__device__ __forceinline__ float2 unpack2(ull v) {
    float2 r; asm("mov.b64 {%0,%1}, %2;" : "=f"(r.x), "=f"(r.y) : "l"(v)); return r;
}

// tanh(x) = 1 - 2/(exp(2x)+1); EX2-based, branchless, saturates via inf/0.
__device__ __forceinline__ float tanh_fast(float x) {
    float e = __expf(2.f * x);
    return 1.f - __fdividef(2.f, e + 1.f);
}
// lipswish(x) = 0.909 * x * sigmoid(x), EX2-based.
__device__ __forceinline__ float lipswish_fast(float x) {
    float ax = 0.909f * x;
    return ax * __fdividef(1.f, 1.f + __expf(-x));
}

__global__ void __launch_bounds__(32) sde_scan_kernel(
    const float* __restrict__ ts, const float* __restrict__ ys,
    const float* __restrict__ iW1, const float* __restrict__ ib1,
    const float* __restrict__ iW2, const float* __restrict__ ib2,
    const float* __restrict__ vW1, const float* __restrict__ vb1,
    const float* __restrict__ vW2, const float* __restrict__ vb2,
    const float* __restrict__ cW1, const float* __restrict__ cb1,
    const float* __restrict__ cW2, const float* __restrict__ cb2,
    const float* __restrict__ rW, const float* __restrict__ rb,
    float* __restrict__ out)
{
    const int b    = blockIdx.x;
    const int lane = threadIdx.x & 31;

    __shared__ __align__(16) float  s_y[16];      // y(n)
    __shared__ __align__(16) float  s_hv[16];     // v-hidden
    __shared__ __align__(16) float2 s_hc2[16];    // c-hidden, duplicated (h,h)

    const float t0 = ts[0];
    const float* __restrict__ ysb = ys + (size_t)b * (T_STEPS * 8);

    const int hidx  = lane >> 1;      // h for g rows, f row, y slot
    const int khalf = lane & 1;

    // ---- P1 weights: row = lane; [t-coef | 16 y-coefs] ----
    float w1[16], w1t, b1r;
    {
        const float* W = (lane < 16) ? (vW1 + lane * 17) : (cW1 + (lane - 16) * 17);
        w1t = W[0];
#pragma unroll
        for (int k = 0; k < 16; k++) w1[k] = W[1 + k];
        b1r = (lane < 16) ? vb1[lane] : cb1[lane - 16];
    }

    // ---- g packed weights: rows 4l..4l+3 (flat = hidx*8 + khalf*4 + j) ----
    ull cwp01[16], cwp23[16];
    float cbr0, cbr1, cbr2, cbr3;
    {
        const int fl = 4 * lane;
        const float* Wa = cW2 + (fl + 0) * 16;
        const float* Wb = cW2 + (fl + 1) * 16;
        const float* Wc = cW2 + (fl + 2) * 16;
        const float* Wd = cW2 + (fl + 3) * 16;
#pragma unroll
        for (int k = 0; k < 16; k++) {
            cwp01[k] = pack2(Wa[k], Wb[k]);
            cwp23[k] = pack2(Wc[k], Wd[k]);
        }
        cbr0 = cb2[fl]; cbr1 = cb2[fl + 1]; cbr2 = cb2[fl + 2]; cbr3 = cb2[fl + 3];
    }

    // ---- f weights: row hidx, K-half khalf ----
    float vfh[8], fbb;
    {
#pragma unroll
        for (int k = 0; k < 8; k++) vfh[k] = vW2[hidx * 16 + khalf * 8 + k];
        fbb = (khalf == 0) ? vb2[hidx] : 0.f;
    }

    // ---- initial MLP: y0 = relu([t0, ys0] @ iW1^T + ib1) @ iW2^T + ib2 ----
    {
        float a = 0.f;
        if (lane < 16) {
            a = fmaf(iW1[lane * 9], t0, ib1[lane]);
#pragma unroll
            for (int k = 0; k < 8; k++) a = fmaf(iW1[lane * 9 + 1 + k], ysb[k], a);
            a = fmaxf(a, 0.f);
        }
        float hv[16];
#pragma unroll
        for (int k = 0; k < 16; k++) hv[k] = __shfl_sync(FULLMASK, a, k);
        float y0 = 0.f;
        if (lane < 16) {
            y0 = ib2[lane];
#pragma unroll
            for (int k = 0; k < 16; k++) y0 = fmaf(iW2[lane * 16 + k], hv[k], y0);
            s_y[lane] = y0;
        }
        float yv16[16];
#pragma unroll
        for (int k = 0; k < 16; k++) yv16[k] = __shfl_sync(FULLMASK, y0, k);
        if (lane == 0) {
            float acc = rb[0];
#pragma unroll
            for (int k = 0; k < 16; k++) acc = fmaf(rW[k], yv16[k], acc);
            out[b * 2 + 0] = acc;
        }
    }
    __syncwarp();

    // ---- dx: lane tracks d-quad d0 = khalf*4 ----
    const int d0 = khalf * 4;
    auto ldrow = [&](int r) -> float4 {
        return *reinterpret_cast<const float4*>(ysb + (size_t)r * 8 + d0);
    };

    float tf = t0;

    // ---- one Euler step ----
    auto step = [&](const float4 pv, const float4 cv) {
        // ===== P1: h(row=lane) = lipswish(W1·[t, y] + b1) =====
        {
            const float4* Y4 = reinterpret_cast<const float4*>(s_y);
            float4 q0 = Y4[0], q1 = Y4[1], q2 = Y4[2], q3 = Y4[3];
            float a0 = fmaf(w1t, tf, b1r), a1 = 0.f, a2 = 0.f, a3 = 0.f;
            a0 = fmaf(w1[0],  q0.x, a0); a1 = fmaf(w1[1],  q0.y, a1);
            a2 = fmaf(w1[2],  q0.z, a2); a3 = fmaf(w1[3],  q0.w, a3);
            a0 = fmaf(w1[4],  q1.x, a0); a1 = fmaf(w1[5],  q1.y, a1);
            a2 = fmaf(w1[6],  q1.z, a2); a3 = fmaf(w1[7],  q1.w, a3);
            a0 = fmaf(w1[8],  q2.x, a0); a1 = fmaf(w1[9],  q2.y, a1);
            a2 = fmaf(w1[10], q2.z, a2); a3 = fmaf(w1[11], q2.w, a3);
            a0 = fmaf(w1[12], q3.x, a0); a1 = fmaf(w1[13], q3.y, a1);
            a2 = fmaf(w1[14], q3.z, a2); a3 = fmaf(w1[15], q3.w, a3);
            float h = lipswish_fast((a0 + a1) + (a2 + a3));
            if (lane < 16) s_hv[lane] = h;
            else           s_hc2[lane - 16] = make_float2(h, h);
        }
        tf += 1.f;
        __syncwarp();

        // ===== P2 =====
        float ylane = s_y[hidx];   // early scalar load (y(n)[h])

        // hc duplicated pairs
        ull hc2[16];
        {
            const ulonglong2* H2 = reinterpret_cast<const ulonglong2*>(s_hc2);
#pragma unroll
            for (int q = 0; q < 8; q++) {
                ulonglong2 u = H2[q];
                hc2[2 * q] = u.x; hc2[2 * q + 1] = u.y;
            }
        }
        // two packed dots: rows (4l,4l+1) and (4l+2,4l+3)
        ull A0 = 0, A1 = 0, B0 = 0, B1 = 0;
#pragma unroll
        for (int k = 0; k < 16; k += 2) {
            A0 = fma2(cwp01[k],     hc2[k],     A0);
            A1 = fma2(cwp01[k + 1], hc2[k + 1], A1);
            B0 = fma2(cwp23[k],     hc2[k],     B0);
            B1 = fma2(cwp23[k + 1], hc2[k + 1], B1);
        }
        float2 ua0 = unpack2(A0), ua1 = unpack2(A1);
        float2 ub0 = unpack2(B0), ub1 = unpack2(B1);
        float g0 = tanh_fast((ua0.x + ua1.x) + cbr0);
        float g1 = tanh_fast((ua0.y + ua1.y) + cbr1);
        float g2 = tanh_fast((ub0.x + ub1.x) + cbr2);
        float g3 = tanh_fast((ub0.y + ub1.y) + cbr3);

        // f row hidx, K-half khalf
        float fp;
        {
            const float4* Hv = reinterpret_cast<const float4*>(s_hv);
            float4 va = Hv[khalf * 2 + 0], vb = Hv[khalf * 2 + 1];
            float f0 = fbb, f1 = 0.f, f2 = 0.f, f3 = 0.f;
            f0 = fmaf(vfh[0], va.x, f0); f1 = fmaf(vfh[1], va.y, f1);
            f2 = fmaf(vfh[2], va.z, f2); f3 = fmaf(vfh[3], va.w, f3);
            f0 = fmaf(vfh[4], vb.x, f0); f1 = fmaf(vfh[5], vb.y, f1);
            f2 = fmaf(vfh[6], vb.z, f2); f3 = fmaf(vfh[7], vb.w, f3);
            fp = (f0 + f1) + (f2 + f3);
        }
        fp += __shfl_xor_sync(FULLMASK, fp, 1);
        float fv = tanh_fast(fp);

        // einsum: this lane's d-quad of h = hidx
        float part = g0 * (cv.x - pv.x);
        part = fmaf(g1, cv.y - pv.y, part);
        part = fmaf(g2, cv.z - pv.z, part);
        part = fmaf(g3, cv.w - pv.w, part);
        part += __shfl_xor_sync(FULLMASK, part, 1);

        float ynew = ylane + fv + part;
        if (khalf == 0) s_y[hidx] = ynew;
        __syncwarp();
    };

    // ---- main loop: 4-step bodies with register-rotated row prefetch ----
    float4 rA = ldrow(0), rB = ldrow(1), rC = ldrow(2), rD = ldrow(3);
    int n = 0;
#pragma unroll 1
    for (int it = 0; it < 1023; it++) {   // n = 0..4091, prefetch rows n+4..n+7 <= 4095
        float4 p0 = ldrow(n + 4);
        step(rA, rB);
        float4 p1 = ldrow(n + 5);
        step(rB, rC);
        float4 p2 = ldrow(n + 6);
        step(rC, rD);
        float4 p3 = ldrow(n + 7);
        step(rD, p0);
        rA = p0; rB = p1; rC = p2; rD = p3;
        n += 4;
    }
    // tail: n = 4092, 4093, 4094 (rows already resident)
    step(rA, rB);
    step(rB, rC);
    step(rC, rD);

    // ---- readout of yT ----
    if (lane == 0) {
        float acc = rb[0];
#pragma unroll
        for (int k = 0; k < 16; k++) acc = fmaf(rW[k], s_y[k], acc);
        out[b * 2 + 1] = acc;
    }
}

extern "C" void kernel_launch(void* const* d_in, const int* in_sizes, int n_in,
                              void* d_out, int out_size) {
    const float* ts  = (const float*)d_in[0];
    const float* ys  = (const float*)d_in[1];
    const float* iW1 = (const float*)d_in[2];
    const float* ib1 = (const float*)d_in[3];
    const float* iW2 = (const float*)d_in[4];
    const float* ib2 = (const float*)d_in[5];
    const float* vW1 = (const float*)d_in[6];
    const float* vb1 = (const float*)d_in[7];
    const float* vW2 = (const float*)d_in[8];
    const float* vb2 = (const float*)d_in[9];
    const float* cW1 = (const float*)d_in[10];
    const float* cb1 = (const float*)d_in[11];
    const float* cW2 = (const float*)d_in[12];
    const float* cb2 = (const float*)d_in[13];
    const float* rW  = (const float*)d_in[14];
    const float* rb  = (const float*)d_in[15];

    const int Bn = out_size / 2;  // (B, 2, 1) float32
    sde_scan_kernel<<<Bn, 32>>>(ts, ys, iW1, ib1, iW2, ib2,
                                vW1, vb1, vW2, vb2,
                                cW1, cb1, cW2, cb2, rW, rb,
                                (float*)d_out);
}